// round 1
// baseline (speedup 1.0000x reference)
#include <cuda_runtime.h>
#include <math.h>

// ---------------------------------------------------------------------------
// ProteinEmbeddingPooling — restructured:
//   q0  = emb[:,0,:] @ Wq^T + bq                       [32,1280]
//   kq  = q0 @ Wk           ; cb = q0 . bk             [32,1280], [32]
//   scores[b,s] = scale*(emb[b,s].kq[b] + cb[b]), masked
//   pooled[b]   = softmax_s(scores) . emb[b,:,:]       (online softmax, split-S)
//   ctx = pooled @ Wv^T + bv ; h = ctx @ Wo^T + bo ; LN ; ReLU
// ---------------------------------------------------------------------------

#define BB 32
#define SS 1024
#define DD 1280
#define CTAS_PER_B 8
#define WPB 4                       // warps per CTA in attn kernel
#define NSPL (CTAS_PER_B * WPB)     // 32 warp-splits per batch
#define RPW (SS / NSPL)             // 32 rows per warp

// ---- scratch (device globals; no allocation allowed) ----
__device__ float g_q0[BB * DD];
__device__ float g_kq[BB * DD];
__device__ float g_cb[BB];
__device__ float g_pm[BB * NSPL];
__device__ float g_pl[BB * NSPL];
__device__ float g_pacc[(size_t)BB * NSPL * DD];   // 5.24 MB
__device__ float g_pooled[BB * DD];
__device__ float g_ctx[BB * DD];
__device__ float g_h[BB * DD];

// ---------------------------------------------------------------------------
// init: C matrices start at their bias (gemm kernels atomicAdd partials on top)
// ---------------------------------------------------------------------------
__global__ void init_kernel(const float* __restrict__ bq,
                            const float* __restrict__ bv,
                            const float* __restrict__ bo)
{
    int i = blockIdx.x * blockDim.x + threadIdx.x;
    if (i < BB * DD) {
        int n = i % DD;
        g_q0[i]  = bq[n];
        g_kq[i]  = 0.0f;
        g_ctx[i] = bv[n];
        g_h[i]   = bo[n];
    }
}

// ---------------------------------------------------------------------------
// small GEMM: C[32,1280] += A[32,1280] * op(W), 1280-deep, k-split over grid.y
//   MODE 0: W is [N,K] row-major (C = A . W^T)
//   MODE 1: W is [K,N] row-major (C = A . W)
//   SRC: 0 = A param (with lda), 1 = g_q0, 2 = g_pooled, 3 = g_ctx
//   DST: 0 = g_q0, 1 = g_kq, 2 = g_ctx, 3 = g_h
// grid (20, 8), block 128. Double-buffered smem, 4x4 register blocking.
// ---------------------------------------------------------------------------
template<int MODE, int SRC, int DST>
__global__ void __launch_bounds__(128) gemm32(const float* __restrict__ Aext,
                                              size_t lda,
                                              const float* __restrict__ W)
{
    constexpr int KC = 32;
    constexpr int NT = 64;
    constexpr int KPER = DD / 8;      // 160 k per CTA
    constexpr int NCH  = KPER / KC;   // 5 chunks

    const float* A = (SRC == 0) ? Aext
                   : (SRC == 1) ? g_q0
                   : (SRC == 2) ? g_pooled
                   :              g_ctx;
    if (SRC != 0) lda = DD;
    float* C = (DST == 0) ? g_q0
             : (DST == 1) ? g_kq
             : (DST == 2) ? g_ctx
             :              g_h;

    __shared__ float As[2][KC][33];
    __shared__ float Ws[2][KC][NT + 1];

    const int tid = threadIdx.x;
    const int tm = tid & 7;          // m-group (m = tm + 8i)
    const int tn = tid >> 3;         // n-group (n = tn + 16j)
    const int n0 = blockIdx.x * NT;
    const int k0 = blockIdx.y * KPER;

    float acc[4][4] = {};
    float ra[8], rw[16];

    auto fetch = [&](int kb) {
#pragma unroll
        for (int it = 0; it < 8; it++) {
            int f = tid + it * 128;
            ra[it] = A[(size_t)(f >> 5) * lda + kb + (f & 31)];
        }
        if (MODE == 0) {
#pragma unroll
            for (int it = 0; it < 16; it++) {
                int f = tid + it * 128;
                rw[it] = W[(size_t)(n0 + (f >> 5)) * DD + kb + (f & 31)];
            }
        } else {
#pragma unroll
            for (int it = 0; it < 16; it++) {
                int f = tid + it * 128;
                rw[it] = W[(size_t)(kb + (f >> 6)) * DD + n0 + (f & 63)];
            }
        }
    };
    auto store = [&](int buf) {
#pragma unroll
        for (int it = 0; it < 8; it++) {
            int f = tid + it * 128;
            As[buf][f & 31][f >> 5] = ra[it];
        }
        if (MODE == 0) {
#pragma unroll
            for (int it = 0; it < 16; it++) {
                int f = tid + it * 128;
                Ws[buf][f & 31][f >> 5] = rw[it];
            }
        } else {
#pragma unroll
            for (int it = 0; it < 16; it++) {
                int f = tid + it * 128;
                Ws[buf][f >> 6][f & 63] = rw[it];
            }
        }
    };

    fetch(k0);
    store(0);
    __syncthreads();

    for (int c = 0; c < NCH; c++) {
        const int cur = c & 1;
        if (c + 1 < NCH) fetch(k0 + (c + 1) * KC);   // LDGs overlap compute
#pragma unroll
        for (int k = 0; k < KC; k++) {
            float a[4], w[4];
#pragma unroll
            for (int i = 0; i < 4; i++) a[i] = As[cur][k][tm + 8 * i];
#pragma unroll
            for (int j = 0; j < 4; j++) w[j] = Ws[cur][k][tn + 16 * j];
#pragma unroll
            for (int i = 0; i < 4; i++)
#pragma unroll
                for (int j = 0; j < 4; j++)
                    acc[i][j] = fmaf(a[i], w[j], acc[i][j]);
        }
        __syncthreads();
        if (c + 1 < NCH) {
            store((c + 1) & 1);
            __syncthreads();
        }
    }

#pragma unroll
    for (int i = 0; i < 4; i++)
#pragma unroll
        for (int j = 0; j < 4; j++)
            atomicAdd(&C[(size_t)(tm + 8 * i) * DD + n0 + tn + 16 * j], acc[i][j]);
}

// ---------------------------------------------------------------------------
// cb[b] = q0[b] . bk
// ---------------------------------------------------------------------------
__global__ void __launch_bounds__(256) cb_kernel(const float* __restrict__ bk)
{
    const int b = blockIdx.x, tid = threadIdx.x;
    float s = 0.0f;
    for (int k = tid; k < DD; k += 256)
        s = fmaf(g_q0[b * DD + k], bk[k], s);
    __shared__ float red[256];
    red[tid] = s;
    __syncthreads();
    for (int off = 128; off > 0; off >>= 1) {
        if (tid < off) red[tid] += red[tid + off];
        __syncthreads();
    }
    if (tid == 0) g_cb[b] = red[0];
}

// ---------------------------------------------------------------------------
// attention + pooling: single pass over emb, online softmax per warp-split.
// grid 256 (32 batches x 8 CTAs), block 128 (4 warps, each owns 32 rows).
// Each lane owns 40 columns (10 x float4), acc kept in registers.
// ---------------------------------------------------------------------------
__global__ void __launch_bounds__(128) attn_kernel(const float* __restrict__ emb,
                                                   const int* __restrict__ mask,
                                                   float scale)
{
    const int b = blockIdx.x / CTAS_PER_B;
    const int warp = threadIdx.x >> 5;
    const int lane = threadIdx.x & 31;
    const int split = (blockIdx.x % CTAS_PER_B) * WPB + warp;
    const int s0 = split * RPW;

    const float4* kq4 = reinterpret_cast<const float4*>(g_kq + b * DD);
    float4 kqr[10];
#pragma unroll
    for (int c = 0; c < 10; c++) kqr[c] = kq4[c * 32 + lane];
    const float cb = g_cb[b];

    float m = -INFINITY, l = 0.0f;
    float4 acc[10];
#pragma unroll
    for (int c = 0; c < 10; c++) acc[c] = make_float4(0.f, 0.f, 0.f, 0.f);

    const int* mrow = mask + b * SS;

    for (int r = 0; r < RPW; r++) {
        const int s = s0 + r;
        const float4* row =
            reinterpret_cast<const float4*>(emb + ((size_t)b * SS + s) * DD);
        float4 x[10];
#pragma unroll
        for (int c = 0; c < 10; c++) x[c] = row[c * 32 + lane];

        float p = 0.0f;
#pragma unroll
        for (int c = 0; c < 10; c++) {
            p = fmaf(x[c].x, kqr[c].x, p);
            p = fmaf(x[c].y, kqr[c].y, p);
            p = fmaf(x[c].z, kqr[c].z, p);
            p = fmaf(x[c].w, kqr[c].w, p);
        }
#pragma unroll
        for (int off = 16; off > 0; off >>= 1)
            p += __shfl_xor_sync(0xffffffffu, p, off);

        float score = (p + cb) * scale;
        if (mrow[s] == 0) score = -1e9f;

        const float mn = fmaxf(m, score);
        if (mn > m) {                       // rescale only when max advances
            const float fac = __expf(m - mn);   // first row: exp(-inf)=0
            l *= fac;
#pragma unroll
            for (int c = 0; c < 10; c++) {
                acc[c].x *= fac; acc[c].y *= fac;
                acc[c].z *= fac; acc[c].w *= fac;
            }
            m = mn;
        }
        const float w = __expf(score - m);
        l += w;
#pragma unroll
        for (int c = 0; c < 10; c++) {
            acc[c].x = fmaf(w, x[c].x, acc[c].x);
            acc[c].y = fmaf(w, x[c].y, acc[c].y);
            acc[c].z = fmaf(w, x[c].z, acc[c].z);
            acc[c].w = fmaf(w, x[c].w, acc[c].w);
        }
    }

    const int pidx = b * NSPL + split;
    float4* pa = reinterpret_cast<float4*>(g_pacc + (size_t)pidx * DD);
#pragma unroll
    for (int c = 0; c < 10; c++) pa[c * 32 + lane] = acc[c];
    if (lane == 0) { g_pm[pidx] = m; g_pl[pidx] = l; }
}

// ---------------------------------------------------------------------------
// combine warp-split partials -> pooled[b,:]. grid 32, block 320 (1 float4/thr)
// ---------------------------------------------------------------------------
__global__ void __launch_bounds__(320) combine_kernel()
{
    const int b = blockIdx.x;
    __shared__ float fs[NSPL], ls[NSPL];

    if (threadIdx.x < NSPL) {
        float M = -INFINITY;
#pragma unroll
        for (int p = 0; p < NSPL; p++) M = fmaxf(M, g_pm[b * NSPL + p]);
        const float f = __expf(g_pm[b * NSPL + threadIdx.x] - M);
        fs[threadIdx.x] = f;
        ls[threadIdx.x] = f * g_pl[b * NSPL + threadIdx.x];
    }
    __syncthreads();

    float L = 0.0f;
#pragma unroll
    for (int p = 0; p < NSPL; p++) L += ls[p];
    const float invL = 1.0f / L;

    const int d4 = threadIdx.x;   // 0..319
    float4 sum = make_float4(0.f, 0.f, 0.f, 0.f);
    for (int p = 0; p < NSPL; p++) {
        const float f = fs[p];
        const float4 a = reinterpret_cast<const float4*>(
            g_pacc + (size_t)(b * NSPL + p) * DD)[d4];
        sum.x = fmaf(f, a.x, sum.x);
        sum.y = fmaf(f, a.y, sum.y);
        sum.z = fmaf(f, a.z, sum.z);
        sum.w = fmaf(f, a.w, sum.w);
    }
    reinterpret_cast<float4*>(g_pooled + b * DD)[d4] =
        make_float4(sum.x * invL, sum.y * invL, sum.z * invL, sum.w * invL);
}

// ---------------------------------------------------------------------------
// LayerNorm + ReLU on h[32,1280] -> out. grid 32, block 256, 5 elems/thread.
// ---------------------------------------------------------------------------
__global__ void __launch_bounds__(256) ln_kernel(const float* __restrict__ gamma,
                                                 const float* __restrict__ beta,
                                                 float* __restrict__ out)
{
    const int b = blockIdx.x, tid = threadIdx.x;
    float x[5];
    float s = 0.0f, s2 = 0.0f;
#pragma unroll
    for (int i = 0; i < 5; i++) {
        x[i] = g_h[b * DD + tid + i * 256];
        s += x[i];
        s2 = fmaf(x[i], x[i], s2);
    }
    __shared__ float rs[256], rs2[256];
    rs[tid] = s; rs2[tid] = s2;
    __syncthreads();
    for (int off = 128; off > 0; off >>= 1) {
        if (tid < off) { rs[tid] += rs[tid + off]; rs2[tid] += rs2[tid + off]; }
        __syncthreads();
    }
    const float mu  = rs[0] * (1.0f / DD);
    float var = rs2[0] * (1.0f / DD) - mu * mu;
    var = fmaxf(var, 0.0f);
    const float inv = rsqrtf(var + 1e-5f);
#pragma unroll
    for (int i = 0; i < 5; i++) {
        const int n = tid + i * 256;
        const float v = (x[i] - mu) * inv * gamma[n] + beta[n];
        out[b * DD + n] = fmaxf(v, 0.0f);
    }
}

// ---------------------------------------------------------------------------
extern "C" void kernel_launch(void* const* d_in, const int* in_sizes, int n_in,
                              void* d_out, int out_size)
{
    (void)in_sizes; (void)n_in; (void)out_size;

    const float* emb   = (const float*)d_in[0];
    const int*   mask  = (const int*)d_in[1];
    const float* Wq    = (const float*)d_in[2];
    const float* bq    = (const float*)d_in[3];
    const float* Wk    = (const float*)d_in[4];
    const float* bk    = (const float*)d_in[5];
    const float* Wv    = (const float*)d_in[6];
    const float* bv    = (const float*)d_in[7];
    const float* Wo    = (const float*)d_in[8];
    const float* bo    = (const float*)d_in[9];
    const float* gamma = (const float*)d_in[10];
    const float* beta  = (const float*)d_in[11];
    float* out = (float*)d_out;

    const float scale = 1.0f / sqrtf((float)DD);
    const dim3 ggrid(DD / 64, 8);

    init_kernel<<<(BB * DD + 255) / 256, 256>>>(bq, bv, bo);
    // q0 = emb[:,0,:] @ Wq^T (+bq via init)
    gemm32<0, 0, 0><<<ggrid, 128>>>(emb, (size_t)SS * DD, Wq);
    cb_kernel<<<BB, 256>>>(bk);
    // kq = q0 @ Wk
    gemm32<1, 1, 1><<<ggrid, 128>>>(nullptr, 0, Wk);
    // online-softmax attention pooling over emb (single pass)
    attn_kernel<<<BB * CTAS_PER_B, 128>>>(emb, mask, scale);
    combine_kernel<<<BB, 320>>>();
    // ctx = pooled @ Wv^T (+bv via init)
    gemm32<0, 2, 2><<<ggrid, 128>>>(nullptr, 0, Wv);
    // h = ctx @ Wo^T (+bo via init)
    gemm32<0, 3, 3><<<ggrid, 128>>>(nullptr, 0, Wo);
    // LayerNorm + ReLU -> out
    ln_kernel<<<BB, 256>>>(gamma, beta, out);
}

// round 3
// speedup vs baseline: 1.0409x; 1.0409x over previous
#include <cuda_runtime.h>
#include <math.h>

// ---------------------------------------------------------------------------
// ProteinEmbeddingPooling — restructured:
//   q0  = emb[:,0,:] @ Wq^T + bq                       [32,1280]
//   kq  = q0 @ Wk           ; cb = q0 . bk             [32,1280], [32]
//   scores[b,s] = scale*(emb[b,s].kq[b] + cb[b]), masked
//   pooled[b]   = softmax_s(scores) . emb[b,:,:]       (online softmax, split-S)
//   ctx = pooled @ Wv^T + bv ; h = ctx @ Wo^T + bo ; LN ; ReLU
// ---------------------------------------------------------------------------

#define BB 32
#define SS 1024
#define DD 1280
#define CTAS_PER_B 8
#define WPB 4                       // warps per CTA in attn kernel
#define NSPL (CTAS_PER_B * WPB)     // 32 warp-splits per batch
#define RPW (SS / NSPL)             // 32 rows per warp

// ---- scratch (device globals; no allocation allowed) ----
__device__ float g_q0[BB * DD];
__device__ float g_kq[BB * DD];
__device__ float g_pm[BB * NSPL];
__device__ float g_pl[BB * NSPL];
__device__ float g_pacc[(size_t)BB * NSPL * DD];   // 5.24 MB
__device__ float g_pooled[BB * DD];
__device__ float g_ctx[BB * DD];
__device__ float g_h[BB * DD];

// ---------------------------------------------------------------------------
// init: C matrices start at their bias (gemm kernels atomicAdd partials on top)
// ---------------------------------------------------------------------------
__global__ void init_kernel(const float* __restrict__ bq,
                            const float* __restrict__ bv,
                            const float* __restrict__ bo)
{
    int i = blockIdx.x * blockDim.x + threadIdx.x;
    if (i < BB * DD) {
        int n = i % DD;
        g_q0[i]  = bq[n];
        g_kq[i]  = 0.0f;
        g_ctx[i] = bv[n];
        g_h[i]   = bo[n];
    }
}

// ---------------------------------------------------------------------------
// small GEMM: C[32,1280] += A[32,1280] * op(W)
//   MODE 0: W is [N,K] row-major (C = A . W^T)
//   MODE 1: W is [K,N] row-major (C = A . W)
//   SRC: 0 = Aext param (with lda), 1 = g_q0, 2 = g_pooled, 3 = g_ctx
//        (device globals MUST be resolved in device code, not passed from host)
//   DST: 0 = g_q0, 1 = g_kq, 2 = g_ctx, 3 = g_h
// grid (20, 16): 20 n-tiles of 64, 16 k-splits of 80. block 256 (8 warps).
// ONE k-chunk per CTA: load smem once, no mid-loop syncs, 2x4 register tile.
// ---------------------------------------------------------------------------
template<int MODE, int SRC, int DST>
__global__ void __launch_bounds__(256) gemm32(const float* __restrict__ Aext,
                                              size_t lda,
                                              const float* __restrict__ W)
{
    constexpr int NT = 64;
    constexpr int KC = 80;

    const float* A = (SRC == 0) ? Aext
                   : (SRC == 1) ? g_q0
                   : (SRC == 2) ? g_pooled
                   :              g_ctx;
    if (SRC != 0) lda = DD;
    float* C = (DST == 0) ? g_q0
             : (DST == 1) ? g_kq
             : (DST == 2) ? g_ctx
             :              g_h;

    __shared__ float As[KC][33];        // [k][m]
    __shared__ float Ws[KC][68];        // [k][n], row stride 272B (16B aligned)

    const int tid = threadIdx.x;
    const int n0 = blockIdx.x * NT;
    const int k0 = blockIdx.y * KC;

    // ---- load A tile (32 x 80), store transposed [k][m] ----
#pragma unroll
    for (int i = 0; i < 10; i++) {
        int f = tid + i * 256;          // 0..2559
        int m = f / KC;
        int k = f % KC;
        As[k][m] = A[(size_t)m * lda + k0 + k];
    }

    // ---- load W tile -> Ws[k][n] ----
    const float4* W4 = reinterpret_cast<const float4*>(W);
    if (MODE == 1) {
        // W[k][n] row-major: rows of 64 floats = 16 float4
#pragma unroll
        for (int i = 0; i < 5; i++) {
            int f = tid + i * 256;      // 0..1279
            int kr = f >> 4;
            int nc = f & 15;
            float4 v = W4[(size_t)(k0 + kr) * (DD / 4) + (n0 >> 2) + nc];
            reinterpret_cast<float4*>(&Ws[kr][0])[nc] = v;
        }
    } else {
        // W[n][k] row-major: per n, 20 float4 along k; transpose into Ws
#pragma unroll
        for (int i = 0; i < 5; i++) {
            int f = tid + i * 256;      // 0..1279
            int n = f / 20;
            int kc4 = f % 20;
            float4 v = W4[(size_t)(n0 + n) * (DD / 4) + (k0 >> 2) + kc4];
            Ws[kc4 * 4 + 0][n] = v.x;
            Ws[kc4 * 4 + 1][n] = v.y;
            Ws[kc4 * 4 + 2][n] = v.z;
            Ws[kc4 * 4 + 3][n] = v.w;
        }
    }
    __syncthreads();

    // ---- compute: thread -> m {ty, ty+16} x n {tx*4 .. tx*4+3} ----
    const int tx = tid & 15;
    const int ty = tid >> 4;

    float acc0[4] = {}, acc1[4] = {};
#pragma unroll 8
    for (int k = 0; k < KC; k++) {
        const float a0 = As[k][ty];
        const float a1 = As[k][ty + 16];
        const float4 w = reinterpret_cast<const float4*>(&Ws[k][0])[tx];
        acc0[0] = fmaf(a0, w.x, acc0[0]);
        acc0[1] = fmaf(a0, w.y, acc0[1]);
        acc0[2] = fmaf(a0, w.z, acc0[2]);
        acc0[3] = fmaf(a0, w.w, acc0[3]);
        acc1[0] = fmaf(a1, w.x, acc1[0]);
        acc1[1] = fmaf(a1, w.y, acc1[1]);
        acc1[2] = fmaf(a1, w.z, acc1[2]);
        acc1[3] = fmaf(a1, w.w, acc1[3]);
    }

    float* c0 = &C[(size_t)ty * DD + n0 + tx * 4];
    float* c1 = &C[(size_t)(ty + 16) * DD + n0 + tx * 4];
#pragma unroll
    for (int j = 0; j < 4; j++) atomicAdd(c0 + j, acc0[j]);
#pragma unroll
    for (int j = 0; j < 4; j++) atomicAdd(c1 + j, acc1[j]);
}

// ---------------------------------------------------------------------------
// attention + pooling: single pass over emb, online softmax per warp-split.
// grid 256 (32 batches x 8 CTAs), block 128 (4 warps, each owns 32 rows).
// Each lane owns 40 columns (10 x float4), acc kept in registers.
// cb[b] = q0[b].bk computed redundantly per warp (tiny, L2-hot).
// ---------------------------------------------------------------------------
__global__ void __launch_bounds__(128) attn_kernel(const float* __restrict__ emb,
                                                   const int* __restrict__ mask,
                                                   const float* __restrict__ bk,
                                                   float scale)
{
    const int b = blockIdx.x / CTAS_PER_B;
    const int warp = threadIdx.x >> 5;
    const int lane = threadIdx.x & 31;
    const int split = (blockIdx.x % CTAS_PER_B) * WPB + warp;
    const int s0 = split * RPW;

    const float4* kq4 = reinterpret_cast<const float4*>(g_kq + b * DD);
    float4 kqr[10];
#pragma unroll
    for (int c = 0; c < 10; c++) kqr[c] = kq4[c * 32 + lane];

    // cb = q0[b] . bk  (warp-redundant)
    float cb;
    {
        const float4* q04 = reinterpret_cast<const float4*>(g_q0 + b * DD);
        const float4* bk4 = reinterpret_cast<const float4*>(bk);
        float p = 0.0f;
#pragma unroll
        for (int c = 0; c < 10; c++) {
            const float4 q = q04[c * 32 + lane];
            const float4 k = bk4[c * 32 + lane];
            p = fmaf(q.x, k.x, p); p = fmaf(q.y, k.y, p);
            p = fmaf(q.z, k.z, p); p = fmaf(q.w, k.w, p);
        }
#pragma unroll
        for (int off = 16; off > 0; off >>= 1)
            p += __shfl_xor_sync(0xffffffffu, p, off);
        cb = p;
    }

    float m = -INFINITY, l = 0.0f;
    float4 acc[10];
#pragma unroll
    for (int c = 0; c < 10; c++) acc[c] = make_float4(0.f, 0.f, 0.f, 0.f);

    const int* mrow = mask + b * SS;

    for (int r = 0; r < RPW; r++) {
        const int s = s0 + r;
        const float4* row =
            reinterpret_cast<const float4*>(emb + ((size_t)b * SS + s) * DD);
        float4 x[10];
#pragma unroll
        for (int c = 0; c < 10; c++) x[c] = row[c * 32 + lane];

        float p = 0.0f;
#pragma unroll
        for (int c = 0; c < 10; c++) {
            p = fmaf(x[c].x, kqr[c].x, p);
            p = fmaf(x[c].y, kqr[c].y, p);
            p = fmaf(x[c].z, kqr[c].z, p);
            p = fmaf(x[c].w, kqr[c].w, p);
        }
#pragma unroll
        for (int off = 16; off > 0; off >>= 1)
            p += __shfl_xor_sync(0xffffffffu, p, off);

        float score = (p + cb) * scale;
        if (mrow[s] == 0) score = -1e9f;

        const float mn = fmaxf(m, score);
        if (mn > m) {                       // rescale only when max advances
            const float fac = __expf(m - mn);   // first row: exp(-inf)=0
            l *= fac;
#pragma unroll
            for (int c = 0; c < 10; c++) {
                acc[c].x *= fac; acc[c].y *= fac;
                acc[c].z *= fac; acc[c].w *= fac;
            }
            m = mn;
        }
        const float w = __expf(score - m);
        l += w;
#pragma unroll
        for (int c = 0; c < 10; c++) {
            acc[c].x = fmaf(w, x[c].x, acc[c].x);
            acc[c].y = fmaf(w, x[c].y, acc[c].y);
            acc[c].z = fmaf(w, x[c].z, acc[c].z);
            acc[c].w = fmaf(w, x[c].w, acc[c].w);
        }
    }

    const int pidx = b * NSPL + split;
    float4* pa = reinterpret_cast<float4*>(g_pacc + (size_t)pidx * DD);
#pragma unroll
    for (int c = 0; c < 10; c++) pa[c * 32 + lane] = acc[c];
    if (lane == 0) { g_pm[pidx] = m; g_pl[pidx] = l; }
}

// ---------------------------------------------------------------------------
// combine warp-split partials -> pooled[b,:]. grid 32, block 320 (1 float4/thr)
// ---------------------------------------------------------------------------
__global__ void __launch_bounds__(320) combine_kernel()
{
    const int b = blockIdx.x;
    __shared__ float fs[NSPL], ls[NSPL];

    if (threadIdx.x < NSPL) {
        float M = -INFINITY;
#pragma unroll
        for (int p = 0; p < NSPL; p++) M = fmaxf(M, g_pm[b * NSPL + p]);
        const float f = __expf(g_pm[b * NSPL + threadIdx.x] - M);
        fs[threadIdx.x] = f;
        ls[threadIdx.x] = f * g_pl[b * NSPL + threadIdx.x];
    }
    __syncthreads();

    float L = 0.0f;
#pragma unroll
    for (int p = 0; p < NSPL; p++) L += ls[p];
    const float invL = 1.0f / L;

    const int d4 = threadIdx.x;   // 0..319
    float4 sum = make_float4(0.f, 0.f, 0.f, 0.f);
#pragma unroll 8
    for (int p = 0; p < NSPL; p++) {
        const float f = fs[p];
        const float4 a = reinterpret_cast<const float4*>(
            g_pacc + (size_t)(b * NSPL + p) * DD)[d4];
        sum.x = fmaf(f, a.x, sum.x);
        sum.y = fmaf(f, a.y, sum.y);
        sum.z = fmaf(f, a.z, sum.z);
        sum.w = fmaf(f, a.w, sum.w);
    }
    reinterpret_cast<float4*>(g_pooled + b * DD)[d4] =
        make_float4(sum.x * invL, sum.y * invL, sum.z * invL, sum.w * invL);
}

// ---------------------------------------------------------------------------
// LayerNorm + ReLU on h[32,1280] -> out. grid 32, block 256, 5 elems/thread.
// ---------------------------------------------------------------------------
__global__ void __launch_bounds__(256) ln_kernel(const float* __restrict__ gamma,
                                                 const float* __restrict__ beta,
                                                 float* __restrict__ out)
{
    const int b = blockIdx.x, tid = threadIdx.x;
    float x[5];
    float s = 0.0f, s2 = 0.0f;
#pragma unroll
    for (int i = 0; i < 5; i++) {
        x[i] = g_h[b * DD + tid + i * 256];
        s += x[i];
        s2 = fmaf(x[i], x[i], s2);
    }
    __shared__ float rs[256], rs2[256];
    rs[tid] = s; rs2[tid] = s2;
    __syncthreads();
    for (int off = 128; off > 0; off >>= 1) {
        if (tid < off) { rs[tid] += rs[tid + off]; rs2[tid] += rs2[tid + off]; }
        __syncthreads();
    }
    const float mu  = rs[0] * (1.0f / DD);
    float var = rs2[0] * (1.0f / DD) - mu * mu;
    var = fmaxf(var, 0.0f);
    const float inv = rsqrtf(var + 1e-5f);
#pragma unroll
    for (int i = 0; i < 5; i++) {
        const int n = tid + i * 256;
        const float v = (x[i] - mu) * inv * gamma[n] + beta[n];
        out[b * DD + n] = fmaxf(v, 0.0f);
    }
}

// ---------------------------------------------------------------------------
extern "C" void kernel_launch(void* const* d_in, const int* in_sizes, int n_in,
                              void* d_out, int out_size)
{
    (void)in_sizes; (void)n_in; (void)out_size;

    const float* emb   = (const float*)d_in[0];
    const int*   mask  = (const int*)d_in[1];
    const float* Wq    = (const float*)d_in[2];
    const float* bq    = (const float*)d_in[3];
    const float* Wk    = (const float*)d_in[4];
    const float* bk    = (const float*)d_in[5];
    const float* Wv    = (const float*)d_in[6];
    const float* bv    = (const float*)d_in[7];
    const float* Wo    = (const float*)d_in[8];
    const float* bo    = (const float*)d_in[9];
    const float* gamma = (const float*)d_in[10];
    const float* beta  = (const float*)d_in[11];
    float* out = (float*)d_out;

    const float scale = 1.0f / sqrtf((float)DD);
    const dim3 ggrid(DD / 64, 16);     // 20 n-tiles x 16 k-splits = 320 CTAs

    init_kernel<<<(BB * DD + 255) / 256, 256>>>(bq, bv, bo);
    // q0 = emb[:,0,:] @ Wq^T (+bq via init)   [A = emb rows, lda = S*D]
    gemm32<0, 0, 0><<<ggrid, 256>>>(emb, (size_t)SS * DD, Wq);
    // kq = q0 @ Wk   [SRC=1 -> g_q0 resolved in device code]
    gemm32<1, 1, 1><<<ggrid, 256>>>(nullptr, 0, Wk);
    // online-softmax attention pooling over emb (single pass), cb folded in
    attn_kernel<<<BB * CTAS_PER_B, 128>>>(emb, mask, bk, scale);
    combine_kernel<<<BB, 320>>>();
    // ctx = pooled @ Wv^T (+bv via init)   [SRC=2 -> g_pooled]
    gemm32<0, 2, 2><<<ggrid, 256>>>(nullptr, 0, Wv);
    // h = ctx @ Wo^T (+bo via init)        [SRC=3 -> g_ctx]
    gemm32<0, 3, 3><<<ggrid, 256>>>(nullptr, 0, Wo);
    // LayerNorm + ReLU -> out
    ln_kernel<<<BB, 256>>>(gamma, beta, out);
}

// round 4
// speedup vs baseline: 1.1934x; 1.1464x over previous
#include <cuda_runtime.h>
#include <math.h>

// ---------------------------------------------------------------------------
// ProteinEmbeddingPooling — restructured:
//   q0  = emb[:,0,:] @ Wq^T + bq ; kq = q0 @ Wk ; cb = q0 . bk
//   scores[b,s] = scale*(emb[b,s].kq[b] + cb[b])  (mask)
//   pooled[b]   = softmax_s(scores) . emb[b,:,:]   (online softmax, split-S)
//   ctx = pooled @ Wv^T + bv ; h = ctx @ Wo^T + bo ; LN ; ReLU
// ---------------------------------------------------------------------------

#define BB 32
#define SS 1024
#define DD 1280
#define CTAS_PER_B 16
#define WPB 4
#define NCP CTAS_PER_B                   // combined partials per batch (CTA-level)
#define RPW (SS / (CTAS_PER_B * WPB))    // 16 rows per warp

// ---- scratch (device globals; no allocation allowed) ----
__device__ float g_q0[BB * DD];
__device__ float g_kq[BB * DD];
__device__ float g_pm[BB * NCP];
__device__ float g_pl[BB * NCP];
__device__ float g_pacc[(size_t)BB * NCP * DD];   // 2.6 MB
__device__ float g_pooled[BB * DD];
__device__ float g_ctx[BB * DD];
__device__ float g_h[BB * DD];

// ---------------------------------------------------------------------------
__global__ void init_kernel(const float* __restrict__ bq,
                            const float* __restrict__ bv,
                            const float* __restrict__ bo)
{
    int i = blockIdx.x * blockDim.x + threadIdx.x;
    if (i < BB * DD) {
        int n = i % DD;
        g_q0[i]  = bq[n];
        g_kq[i]  = 0.0f;
        g_ctx[i] = bv[n];
        g_h[i]   = bo[n];
    }
}

// ---------------------------------------------------------------------------
// small GEMM: C[32,1280] += A[32,1280] * op(W)
//   MODE 0: W [N,K] row-major (C = A.W^T) ; MODE 1: W [K,N] row-major (C = A.W)
//   SRC: 0 = Aext(lda), 1 = g_q0, 2 = g_pooled, 3 = g_ctx   (resolved on device)
//   DST: 0 = g_q0, 1 = g_kq, 2 = g_ctx, 3 = g_h
// grid (20, 32): 64-wide n-tiles, 40-deep k-splits => 640 CTAs (one full wave).
// ---------------------------------------------------------------------------
template<int MODE, int SRC, int DST>
__global__ void __launch_bounds__(256) gemm32(const float* __restrict__ Aext,
                                              size_t lda,
                                              const float* __restrict__ W)
{
    constexpr int NT = 64;
    constexpr int KC = 40;

    const float* A = (SRC == 0) ? Aext
                   : (SRC == 1) ? g_q0
                   : (SRC == 2) ? g_pooled
                   :              g_ctx;
    if (SRC != 0) lda = DD;
    float* C = (DST == 0) ? g_q0
             : (DST == 1) ? g_kq
             : (DST == 2) ? g_ctx
             :              g_h;

    __shared__ float As[KC][33];     // [k][m]
    __shared__ float Ws[KC][68];     // [k][n]

    const int tid = threadIdx.x;
    const int n0 = blockIdx.x * NT;
    const int k0 = blockIdx.y * KC;
    const int k04 = k0 >> 2;

    // ---- A tile (32 x 40) via float4, transposed into As[k][m] ----
    const float4* A4 = reinterpret_cast<const float4*>(A);
    const size_t lda4 = lda >> 2;
#pragma unroll
    for (int i = 0; i < 2; i++) {
        int f = tid + i * 256;          // 0..511, need <320
        if (f < 320) {
            int m = f / 10, kc4 = f % 10;
            float4 v = A4[(size_t)m * lda4 + k04 + kc4];
            As[kc4 * 4 + 0][m] = v.x;
            As[kc4 * 4 + 1][m] = v.y;
            As[kc4 * 4 + 2][m] = v.z;
            As[kc4 * 4 + 3][m] = v.w;
        }
    }

    // ---- W tile -> Ws[k][n] ----
    const float4* W4 = reinterpret_cast<const float4*>(W);
    if (MODE == 1) {
#pragma unroll
        for (int i = 0; i < 3; i++) {
            int f = tid + i * 256;      // need <640
            if (f < 640) {
                int kr = f >> 4, nc = f & 15;
                float4 v = W4[(size_t)(k0 + kr) * (DD / 4) + (n0 >> 2) + nc];
                reinterpret_cast<float4*>(&Ws[kr][0])[nc] = v;
            }
        }
    } else {
#pragma unroll
        for (int i = 0; i < 3; i++) {
            int f = tid + i * 256;
            if (f < 640) {
                int n = f / 10, kc4 = f % 10;
                float4 v = W4[(size_t)(n0 + n) * (DD / 4) + k04 + kc4];
                Ws[kc4 * 4 + 0][n] = v.x;
                Ws[kc4 * 4 + 1][n] = v.y;
                Ws[kc4 * 4 + 2][n] = v.z;
                Ws[kc4 * 4 + 3][n] = v.w;
            }
        }
    }
    __syncthreads();

    // ---- compute: m {ty, ty+16} x n {tx*4..tx*4+3} ----
    const int tx = tid & 15;
    const int ty = tid >> 4;

    float acc0[4] = {}, acc1[4] = {};
#pragma unroll 8
    for (int k = 0; k < KC; k++) {
        const float a0 = As[k][ty];
        const float a1 = As[k][ty + 16];
        const float4 w = reinterpret_cast<const float4*>(&Ws[k][0])[tx];
        acc0[0] = fmaf(a0, w.x, acc0[0]);
        acc0[1] = fmaf(a0, w.y, acc0[1]);
        acc0[2] = fmaf(a0, w.z, acc0[2]);
        acc0[3] = fmaf(a0, w.w, acc0[3]);
        acc1[0] = fmaf(a1, w.x, acc1[0]);
        acc1[1] = fmaf(a1, w.y, acc1[1]);
        acc1[2] = fmaf(a1, w.z, acc1[2]);
        acc1[3] = fmaf(a1, w.w, acc1[3]);
    }

    float* c0 = &C[(size_t)ty * DD + n0 + tx * 4];
    float* c1 = &C[(size_t)(ty + 16) * DD + n0 + tx * 4];
#pragma unroll
    for (int j = 0; j < 4; j++) atomicAdd(c0 + j, acc0[j]);
#pragma unroll
    for (int j = 0; j < 4; j++) atomicAdd(c1 + j, acc1[j]);
}

// ---------------------------------------------------------------------------
// attention + pooling: single pass over emb, online softmax.
// grid 512 (32 batches x 16 CTAs), block 128 (4 warps x 16 rows each).
// kq in smem; next-row loads prefetched; 4 warps merged in-CTA -> 16 partials/b.
// ---------------------------------------------------------------------------
__global__ void __launch_bounds__(128) attn_kernel(const float* __restrict__ emb,
                                                   const int* __restrict__ mask,
                                                   const float* __restrict__ bk,
                                                   float scale)
{
    __shared__ float skq[DD];
    __shared__ float4 sacc[WPB][DD / 4];
    __shared__ float sm[WPB], sl[WPB], scb;

    const int b = blockIdx.x / CTAS_PER_B;
    const int cta = blockIdx.x % CTAS_PER_B;
    const int tid = threadIdx.x;
    const int warp = tid >> 5;
    const int lane = tid & 31;
    const int split = cta * WPB + warp;
    const int s0 = split * RPW;

    // kq -> smem (cooperative)
    {
        const float4* src = reinterpret_cast<const float4*>(g_kq + b * DD);
        float4* dst = reinterpret_cast<float4*>(skq);
        for (int i = tid; i < DD / 4; i += 128) dst[i] = src[i];
    }
    // cb = q0[b].bk by warp 0
    if (warp == 0) {
        const float4* q04 = reinterpret_cast<const float4*>(g_q0 + b * DD);
        const float4* bk4 = reinterpret_cast<const float4*>(bk);
        float p = 0.0f;
#pragma unroll
        for (int c = 0; c < 10; c++) {
            const float4 q = q04[c * 32 + lane];
            const float4 k = bk4[c * 32 + lane];
            p = fmaf(q.x, k.x, p); p = fmaf(q.y, k.y, p);
            p = fmaf(q.z, k.z, p); p = fmaf(q.w, k.w, p);
        }
#pragma unroll
        for (int off = 16; off > 0; off >>= 1)
            p += __shfl_xor_sync(0xffffffffu, p, off);
        if (lane == 0) scb = p;
    }

    // prefetch first row before the sync
    const float* base = emb + (size_t)b * SS * DD;
    float4 x[10];
    {
        const float4* row = reinterpret_cast<const float4*>(base + (size_t)s0 * DD);
#pragma unroll
        for (int c = 0; c < 10; c++) x[c] = row[c * 32 + lane];
    }
    const int* mrow = mask + b * SS;

    __syncthreads();
    const float cb = scb;

    float m = -INFINITY, l = 0.0f;
    float4 acc[10];
#pragma unroll
    for (int c = 0; c < 10; c++) acc[c] = make_float4(0.f, 0.f, 0.f, 0.f);

#pragma unroll 4
    for (int r = 0; r < RPW; r++) {
        const int s = s0 + r;
        const int mk = mrow[s];

        // prefetch next row (clamped on last iter)
        float4 y[10];
        {
            const int rn = (r + 1 < RPW) ? r + 1 : r;
            const float4* nrow =
                reinterpret_cast<const float4*>(base + (size_t)(s0 + rn) * DD);
#pragma unroll
            for (int c = 0; c < 10; c++) y[c] = nrow[c * 32 + lane];
        }

        // score = scale*(x . kq + cb)
        float p = 0.0f;
        const float4* kq4 = reinterpret_cast<const float4*>(skq);
#pragma unroll
        for (int c = 0; c < 10; c++) {
            const float4 k = kq4[c * 32 + lane];
            p = fmaf(x[c].x, k.x, p);
            p = fmaf(x[c].y, k.y, p);
            p = fmaf(x[c].z, k.z, p);
            p = fmaf(x[c].w, k.w, p);
        }
#pragma unroll
        for (int off = 16; off > 0; off >>= 1)
            p += __shfl_xor_sync(0xffffffffu, p, off);

        float score = (p + cb) * scale;
        if (mk == 0) score = -1e9f;

        const float mn = fmaxf(m, score);
        if (mn > m) {
            const float fac = __expf(m - mn);
            l *= fac;
#pragma unroll
            for (int c = 0; c < 10; c++) {
                acc[c].x *= fac; acc[c].y *= fac;
                acc[c].z *= fac; acc[c].w *= fac;
            }
            m = mn;
        }
        const float w = __expf(score - m);
        l += w;
#pragma unroll
        for (int c = 0; c < 10; c++) {
            acc[c].x = fmaf(w, x[c].x, acc[c].x);
            acc[c].y = fmaf(w, x[c].y, acc[c].y);
            acc[c].z = fmaf(w, x[c].z, acc[c].z);
            acc[c].w = fmaf(w, x[c].w, acc[c].w);
        }
#pragma unroll
        for (int c = 0; c < 10; c++) x[c] = y[c];
    }

    // ---- CTA-level merge of 4 warp partials -> 1 partial ----
#pragma unroll
    for (int c = 0; c < 10; c++) sacc[warp][c * 32 + lane] = acc[c];
    if (lane == 0) { sm[warp] = m; sl[warp] = l; }
    __syncthreads();

    const float M = fmaxf(fmaxf(sm[0], sm[1]), fmaxf(sm[2], sm[3]));
    const float f0 = __expf(sm[0] - M), f1 = __expf(sm[1] - M);
    const float f2 = __expf(sm[2] - M), f3 = __expf(sm[3] - M);
    const float L = f0 * sl[0] + f1 * sl[1] + f2 * sl[2] + f3 * sl[3];

    const int pidx = b * NCP + cta;
    float4* pa = reinterpret_cast<float4*>(g_pacc + (size_t)pidx * DD);
#pragma unroll
    for (int i = 0; i < 3; i++) {
        const int idx = tid + i * 128;
        if (idx < DD / 4) {
            const float4 a0 = sacc[0][idx], a1 = sacc[1][idx];
            const float4 a2 = sacc[2][idx], a3 = sacc[3][idx];
            float4 s;
            s.x = fmaf(f0, a0.x, fmaf(f1, a1.x, fmaf(f2, a2.x, f3 * a3.x)));
            s.y = fmaf(f0, a0.y, fmaf(f1, a1.y, fmaf(f2, a2.y, f3 * a3.y)));
            s.z = fmaf(f0, a0.z, fmaf(f1, a1.z, fmaf(f2, a2.z, f3 * a3.z)));
            s.w = fmaf(f0, a0.w, fmaf(f1, a1.w, fmaf(f2, a2.w, f3 * a3.w)));
            pa[idx] = s;
        }
    }
    if (tid == 0) { g_pm[pidx] = M; g_pl[pidx] = L; }
}

// ---------------------------------------------------------------------------
// combine 16 CTA-partials -> pooled[b,:]. grid 32, block 320.
// ---------------------------------------------------------------------------
__global__ void __launch_bounds__(320) combine_kernel()
{
    const int b = blockIdx.x;
    __shared__ float fs[NCP], ls[NCP];

    if (threadIdx.x < NCP) {
        float M = -INFINITY;
#pragma unroll
        for (int p = 0; p < NCP; p++) M = fmaxf(M, g_pm[b * NCP + p]);
        const float f = __expf(g_pm[b * NCP + threadIdx.x] - M);
        fs[threadIdx.x] = f;
        ls[threadIdx.x] = f * g_pl[b * NCP + threadIdx.x];
    }
    __syncthreads();

    float L = 0.0f;
#pragma unroll
    for (int p = 0; p < NCP; p++) L += ls[p];
    const float invL = 1.0f / L;

    const int d4 = threadIdx.x;   // 0..319
    float4 sum = make_float4(0.f, 0.f, 0.f, 0.f);
#pragma unroll
    for (int p = 0; p < NCP; p++) {
        const float f = fs[p];
        const float4 a = reinterpret_cast<const float4*>(
            g_pacc + (size_t)(b * NCP + p) * DD)[d4];
        sum.x = fmaf(f, a.x, sum.x);
        sum.y = fmaf(f, a.y, sum.y);
        sum.z = fmaf(f, a.z, sum.z);
        sum.w = fmaf(f, a.w, sum.w);
    }
    reinterpret_cast<float4*>(g_pooled + b * DD)[d4] =
        make_float4(sum.x * invL, sum.y * invL, sum.z * invL, sum.w * invL);
}

// ---------------------------------------------------------------------------
// LayerNorm + ReLU on h[32,1280] -> out. grid 32, block 256.
// ---------------------------------------------------------------------------
__global__ void __launch_bounds__(256) ln_kernel(const float* __restrict__ gamma,
                                                 const float* __restrict__ beta,
                                                 float* __restrict__ out)
{
    const int b = blockIdx.x, tid = threadIdx.x;
    float x[5];
    float s = 0.0f, s2 = 0.0f;
#pragma unroll
    for (int i = 0; i < 5; i++) {
        x[i] = g_h[b * DD + tid + i * 256];
        s += x[i];
        s2 = fmaf(x[i], x[i], s2);
    }
    __shared__ float rs[256], rs2[256];
    rs[tid] = s; rs2[tid] = s2;
    __syncthreads();
    for (int off = 128; off > 0; off >>= 1) {
        if (tid < off) { rs[tid] += rs[tid + off]; rs2[tid] += rs2[tid + off]; }
        __syncthreads();
    }
    const float mu  = rs[0] * (1.0f / DD);
    float var = rs2[0] * (1.0f / DD) - mu * mu;
    var = fmaxf(var, 0.0f);
    const float inv = rsqrtf(var + 1e-5f);
#pragma unroll
    for (int i = 0; i < 5; i++) {
        const int n = tid + i * 256;
        const float v = (x[i] - mu) * inv * gamma[n] + beta[n];
        out[b * DD + n] = fmaxf(v, 0.0f);
    }
}

// ---------------------------------------------------------------------------
extern "C" void kernel_launch(void* const* d_in, const int* in_sizes, int n_in,
                              void* d_out, int out_size)
{
    (void)in_sizes; (void)n_in; (void)out_size;

    const float* emb   = (const float*)d_in[0];
    const int*   mask  = (const int*)d_in[1];
    const float* Wq    = (const float*)d_in[2];
    const float* bq    = (const float*)d_in[3];
    const float* Wk    = (const float*)d_in[4];
    const float* bk    = (const float*)d_in[5];
    const float* Wv    = (const float*)d_in[6];
    const float* bv    = (const float*)d_in[7];
    const float* Wo    = (const float*)d_in[8];
    const float* bo    = (const float*)d_in[9];
    const float* gamma = (const float*)d_in[10];
    const float* beta  = (const float*)d_in[11];
    float* out = (float*)d_out;

    const float scale = 1.0f / sqrtf((float)DD);
    const dim3 ggrid(DD / 64, 32);   // 20 n-tiles x 32 k-splits = 640 CTAs

    init_kernel<<<(BB * DD + 255) / 256, 256>>>(bq, bv, bo);
    gemm32<0, 0, 0><<<ggrid, 256>>>(emb, (size_t)SS * DD, Wq);     // q0
    gemm32<1, 1, 1><<<ggrid, 256>>>(nullptr, 0, Wk);               // kq = q0@Wk
    attn_kernel<<<BB * CTAS_PER_B, 128>>>(emb, mask, bk, scale);   // pool
    combine_kernel<<<BB, 320>>>();
    gemm32<0, 2, 2><<<ggrid, 256>>>(nullptr, 0, Wv);               // ctx
    gemm32<0, 3, 3><<<ggrid, 256>>>(nullptr, 0, Wo);               // h
    ln_kernel<<<BB, 256>>>(gamma, beta, out);
}